// round 10
// baseline (speedup 1.0000x reference)
#include <cuda_runtime.h>
#include <cuda_bf16.h>
#include <math.h>
#include <stdint.h>

#define TB 16
#define TS 512
#define TE 1024
#define TH 16
#define TD 64
#define KSPLIT 3072          // 3 * TE (bf16 hi|mid|lo splits along K)

// Scratch (device globals: allocation-free rule)
static __device__ float  g_Q[(size_t)TB * TS * TE];
static __device__ float  g_K[(size_t)TB * TS * TE];
static __device__ double g_colpart[TB * TH * TS];
static __device__ double g_logits[TB * TS];
static __device__ __align__(128) __nv_bfloat16 g_As[(size_t)TB * TS * KSPLIT]; // tokens split
static __device__ __align__(128) __nv_bfloat16 g_Ws[(size_t)2 * TE * KSPLIT];  // Wq/Wk split

// ---------------------------------------------------------------------------
// PTX helpers (sm_80-class only: mma.sync / ldmatrix / cp.async — NO tcgen05,
// the harness PTX target is plain sm_103 which rejects 'a'-suffix features)
// ---------------------------------------------------------------------------
__device__ __forceinline__ uint32_t smem_u32(const void* p) {
    uint32_t a;
    asm("{ .reg .u64 t; cvta.to.shared.u64 t, %1; cvt.u32.u64 %0, t; }" : "=r"(a) : "l"(p));
    return a;
}
#define SW128(o) ((o) ^ ((((uint32_t)(o)) >> 3) & 0x70u))

#define CP_ASYNC16(dst, src) \
    asm volatile("cp.async.cg.shared.global [%0], [%1], 16;" :: "r"(dst), "l"(src))
#define CP_COMMIT()  asm volatile("cp.async.commit_group;" ::: "memory")
#define CP_WAIT1()   asm volatile("cp.async.wait_group 1;" ::: "memory")
#define CP_WAIT0()   asm volatile("cp.async.wait_group 0;" ::: "memory")

#define LDSM_X4(r0, r1, r2, r3, a) \
    asm volatile("ldmatrix.sync.aligned.m8n8.x4.shared.b16 {%0,%1,%2,%3}, [%4];" \
                 : "=r"(r0), "=r"(r1), "=r"(r2), "=r"(r3) : "r"(a))

#define MMA_16816(D, A, B0, B1) \
    asm volatile("mma.sync.aligned.m16n8k16.row.col.f32.bf16.bf16.f32 " \
                 "{%0,%1,%2,%3}, {%4,%5,%6,%7}, {%8,%9}, {%0,%1,%2,%3};" \
                 : "+f"((D)[0]), "+f"((D)[1]), "+f"((D)[2]), "+f"((D)[3]) \
                 : "r"((A)[0]), "r"((A)[1]), "r"((A)[2]), "r"((A)[3]), \
                   "r"(B0), "r"(B1))

// ---------------------------------------------------------------------------
// Exact 3-way bf16 split: x == hi + mid + lo (residuals exactly representable)
// ---------------------------------------------------------------------------
__device__ __forceinline__ void split3(float x, unsigned short& h, unsigned short& m,
                                       unsigned short& l) {
    __nv_bfloat16 bh = __float2bfloat16_rn(x);
    float r  = x - __bfloat162float(bh);
    __nv_bfloat16 bm = __float2bfloat16_rn(r);
    float r2 = r - __bfloat162float(bm);
    __nv_bfloat16 bl = __float2bfloat16_rn(r2);
    h = __bfloat16_as_ushort(bh);
    m = __bfloat16_as_ushort(bm);
    l = __bfloat16_as_ushort(bl);
}

__device__ __forceinline__ void split_store4(const float4 v, __nv_bfloat16* dst) {
    unsigned short h[4], m[4], l[4];
    split3(v.x, h[0], m[0], l[0]);
    split3(v.y, h[1], m[1], l[1]);
    split3(v.z, h[2], m[2], l[2]);
    split3(v.w, h[3], m[3], l[3]);
    uint2 uh = make_uint2((uint32_t)h[0] | ((uint32_t)h[1] << 16),
                          (uint32_t)h[2] | ((uint32_t)h[3] << 16));
    uint2 um = make_uint2((uint32_t)m[0] | ((uint32_t)m[1] << 16),
                          (uint32_t)m[2] | ((uint32_t)m[3] << 16));
    uint2 ul = make_uint2((uint32_t)l[0] | ((uint32_t)l[1] << 16),
                          (uint32_t)l[2] | ((uint32_t)l[3] << 16));
    *(uint2*)(dst)            = uh;
    *(uint2*)(dst + TE)       = um;
    *(uint2*)(dst + 2 * TE)   = ul;
}

// tokens [8192,1024] fp32 -> g_As [8192, 3072] bf16 (hi|mid|lo thirds)
__global__ __launch_bounds__(256) void split_tokens_kernel(const float* __restrict__ x)
{
    size_t i = (size_t)blockIdx.x * 256 + threadIdx.x;     // float4 index
    float4 v = ((const float4*)x)[i];
    size_t row = i >> 8;
    int    c4  = (int)(i & 255) * 4;
    split_store4(v, g_As + row * KSPLIT + c4);
}

// Wq/Wk [1024,1024] fp32 -> g_Ws [2][1024, 3072] bf16
__global__ __launch_bounds__(256) void split_w_kernel(const float* __restrict__ Wq,
                                                      const float* __restrict__ Wk)
{
    const float* W = (blockIdx.z == 0) ? Wq : Wk;
    size_t i = (size_t)blockIdx.x * 256 + threadIdx.x;
    float4 v = ((const float4*)W)[i];
    size_t row = i >> 8;
    int    c4  = (int)(i & 255) * 4;
    split_store4(v, g_Ws + (size_t)blockIdx.z * TE * KSPLIT + row * KSPLIT + c4);
}

// ---------------------------------------------------------------------------
// HMMA GEMM (unchanged): 6-term bf16-split product
// ---------------------------------------------------------------------------
#define GEMM_STAGES 3
#define GEMM_STAGE_BYTES 32768                 // A 16KB + B 16KB
#define GEMM_SMEM (GEMM_STAGES * GEMM_STAGE_BYTES)
#define NCHUNK 96                              // 6 segs * 16 chunks of k64

__global__ __launch_bounds__(256) void gemm_hmma_kernel(const float* __restrict__ bq,
                                                        const float* __restrict__ bk)
{
    extern __shared__ char dsm[];
    const uint32_t smem_base = smem_u32(dsm);

    const int t    = threadIdx.x;
    const int lane = t & 31, wid = t >> 5;
    const int warp_m = wid & 3;
    const int warp_n = wid >> 2;
    const int sel = blockIdx.z;
    const int m0  = blockIdx.y * 128;
    const int n0  = blockIdx.x * 128;

    float*       C    = sel ? g_K : g_Q;
    const float* bias = sel ? bk : bq;

    const int row  = t >> 1;
    const int half = t & 1;
    const char* aG = (const char*)(g_As + (size_t)(m0 + row) * KSPLIT + half * 32);
    const char* bG = (const char*)(g_Ws + (size_t)sel * TE * KSPLIT
                                        + (size_t)(n0 + row) * KSPLIT + half * 32);
    uint32_t dOffA[4], dOffB[4];
#pragma unroll
    for (int i = 0; i < 4; i++) {
        uint32_t o = SW128((uint32_t)(row * 128 + half * 64 + i * 16));
        dOffA[i] = o;
        dOffB[i] = 16384u + o;
    }
    const uint32_t segA = 0x0010210u;   // [0,1,2,0,1,0]
    const uint32_t segB = 0x0211000u;   // [0,0,0,1,1,2]

#define ISSUE_STAGE(c_) do {                                                   \
    int _c = (c_);                                                             \
    int _seg = _c >> 4, _kc = _c & 15;                                         \
    int _pa = (segA >> (_seg * 4)) & 7, _pb = (segB >> (_seg * 4)) & 7;        \
    uint32_t _sb = smem_base + (_c % GEMM_STAGES) * GEMM_STAGE_BYTES;          \
    const char* _as = aG + (_pa * 1024 + _kc * 64) * 2;                        \
    const char* _bs = bG + (_pb * 1024 + _kc * 64) * 2;                        \
    _Pragma("unroll")                                                          \
    for (int _i = 0; _i < 4; _i++) {                                           \
        CP_ASYNC16(_sb + dOffA[_i], _as + _i * 16);                            \
        CP_ASYNC16(_sb + dOffB[_i], _bs + _i * 16);                            \
    }                                                                          \
    CP_COMMIT();                                                               \
} while (0)

    float acc[2][8][4];
#pragma unroll
    for (int i = 0; i < 2; i++)
#pragma unroll
        for (int j = 0; j < 8; j++)
#pragma unroll
            for (int k = 0; k < 4; k++) acc[i][j][k] = 0.f;

    const uint32_t lrow = lane & 15;
    const uint32_t lcol = (lane >> 4) * 16;

    ISSUE_STAGE(0);
    ISSUE_STAGE(1);

    for (int c = 0; c < NCHUNK; c++) {
        if (c < NCHUNK - 1) CP_WAIT1(); else CP_WAIT0();
        __syncthreads();
        if (c + 2 < NCHUNK) ISSUE_STAGE(c + 2);

        const uint32_t sb  = smem_base + (c % GEMM_STAGES) * GEMM_STAGE_BYTES;
        const uint32_t aRow = (uint32_t)(warp_m * 32) + lrow;
        const uint32_t bRow = (uint32_t)(warp_n * 64) + lrow;

#pragma unroll
        for (int kk = 0; kk < 4; kk++) {
            uint32_t a[2][4];
#pragma unroll
            for (int mt = 0; mt < 2; mt++) {
                uint32_t off = (aRow + mt * 16) * 128 + kk * 32 + lcol;
                LDSM_X4(a[mt][0], a[mt][1], a[mt][2], a[mt][3], sb + SW128(off));
            }
            uint32_t b[4][4];
#pragma unroll
            for (int nt2 = 0; nt2 < 4; nt2++) {
                uint32_t off = (bRow + nt2 * 16) * 128 + kk * 32 + lcol;
                LDSM_X4(b[nt2][0], b[nt2][1], b[nt2][2], b[nt2][3],
                        sb + 16384u + SW128(off));
            }
#pragma unroll
            for (int mt = 0; mt < 2; mt++)
#pragma unroll
                for (int nt2 = 0; nt2 < 4; nt2++) {
                    MMA_16816(acc[mt][nt2 * 2 + 0], a[mt], b[nt2][0], b[nt2][2]);
                    MMA_16816(acc[mt][nt2 * 2 + 1], a[mt], b[nt2][1], b[nt2][3]);
                }
        }
    }

    const int er = lane >> 2;
    const int ec = (lane & 3) * 2;
#pragma unroll
    for (int mt = 0; mt < 2; mt++) {
        const int r0 = m0 + warp_m * 32 + mt * 16 + er;
#pragma unroll
        for (int nt = 0; nt < 8; nt++) {
            const int col = n0 + warp_n * 64 + nt * 8 + ec;
            const float bx = bias[col], by = bias[col + 1];
            float* p = C + (size_t)r0 * TE + col;
            *(float2*)p            = make_float2(acc[mt][nt][0] + bx, acc[mt][nt][1] + by);
            *(float2*)(p + 8 * TE) = make_float2(acc[mt][nt][2] + bx, acc[mt][nt][3] + by);
        }
    }
#undef ISSUE_STAGE
}

// ---------------------------------------------------------------------------
// Fused attention-column kernel v3: grid 256 (one block per (b,h)) — SAME
// work division as the fast R7/R9 version, but Es shrunk to 32-row q-tiles
// (16 qt iterations) => smem 108.5KB => 2 co-resident CTAs/SM => grid 256
// fits in ONE wave (296 slots) with 16 warps/SM for latency hiding.
// Row-order of all accumulations identical to R9 => bit-identical results.
// ---------------------------------------------------------------------------
#define ATTN_SMEM ((32*512 + 64*32 + 64*128) * 4 + 512 * 8 + 32 * 8 * 2)

__global__ __launch_bounds__(256, 2) void attn_col_kernel()
{
    extern __shared__ char smem_raw[];
    float*  Es     = (float*)smem_raw;            // [32][512] exp(scores)
    float*  Qs     = Es + 32 * 512;               // [64k][32r]
    float*  Ks     = Qs + 64 * 32;                // [64k][128s]
    double* colacc = (double*)(Ks + 64 * 128);    // [512]
    double* denom  = colacc + 512;                // [32]
    double* invd   = denom + 32;                  // [32]

    const int t  = threadIdx.x;
    const int tx = t & 15, ty = t >> 4;
    const int bh = blockIdx.x;
    const int b  = bh >> 4, h = bh & 15;

    colacc[t]       = 0.0;
    colacc[t + 256] = 0.0;

    const size_t base = ((size_t)b * TS) * TE + (size_t)h * TD;

    // Q-tile loader lanes: r = row (0..31), qb = t>>5 (8 cols each)
    const int r  = t & 31;
    const int qb = t >> 5;            // 0..7
    // K-tile loader lanes: s_ld = row within 128-tile, hv = 32-col half
    const int s_ld = t & 127;
    const int hv   = t >> 7;          // 0..1

    float4 qreg[2];
    float4 kreg[8];

    // prefetch Q tile qt=0
    {
        const float* qrow = g_Q + base + (size_t)r * TE + qb * 8;
        qreg[0] = *(const float4*)(qrow);
        qreg[1] = *(const float4*)(qrow + 4);
    }

    for (int qt = 0; qt < 16; qt++) {
        __syncthreads();   // previous colacc (Es reads) done before overwrites
        {
#pragma unroll
            for (int c = 0; c < 2; c++) {
                int q = qb * 8 + c * 4;
                Qs[(q+0)*32 + r] = qreg[c].x;
                Qs[(q+1)*32 + r] = qreg[c].y;
                Qs[(q+2)*32 + r] = qreg[c].z;
                Qs[(q+3)*32 + r] = qreg[c].w;
            }
        }
        if (t < 32) denom[t] = 0.0;

        // prefetch K tile kt=0
        {
            const float* krow = g_K + base + (size_t)s_ld * TE + hv * 32;
#pragma unroll
            for (int c = 0; c < 8; c++)
                kreg[c] = *(const float4*)(krow + c * 4);
        }
        __syncthreads();

        for (int kt = 0; kt < 4; kt++) {
            {
#pragma unroll
                for (int c = 0; c < 8; c++) {
                    int q = hv * 8 + c;
                    Ks[(q*4+0)*128 + s_ld] = kreg[c].x;
                    Ks[(q*4+1)*128 + s_ld] = kreg[c].y;
                    Ks[(q*4+2)*128 + s_ld] = kreg[c].z;
                    Ks[(q*4+3)*128 + s_ld] = kreg[c].w;
                }
            }
            __syncthreads();

            // prefetch next K tile (or next Q tile during last kt)
            if (kt < 3) {
                const float* krow = g_K + base + (size_t)((kt+1)*128 + s_ld) * TE + hv * 32;
#pragma unroll
                for (int c = 0; c < 8; c++)
                    kreg[c] = *(const float4*)(krow + c * 4);
            } else if (qt < 15) {
                const float* qrow = g_Q + base + (size_t)((qt+1)*32 + r) * TE + qb * 8;
                qreg[0] = *(const float4*)(qrow);
                qreg[1] = *(const float4*)(qrow + 4);
            }

            float acc[2][8];
#pragma unroll
            for (int i = 0; i < 2; i++)
#pragma unroll
                for (int j = 0; j < 8; j++) acc[i][j] = 0.f;

#pragma unroll 8
            for (int k = 0; k < 64; k++) {
                float2 av = *(const float2*)&Qs[k*32 + ty*2];
                float4 b0 = *(const float4*)&Ks[k*128 + tx*8];
                float4 b1 = *(const float4*)&Ks[k*128 + tx*8 + 4];
                float bb[8] = {b0.x, b0.y, b0.z, b0.w, b1.x, b1.y, b1.z, b1.w};
#pragma unroll
                for (int j = 0; j < 8; j++) {
                    acc[0][j] = fmaf(av.x, bb[j], acc[0][j]);
                    acc[1][j] = fmaf(av.y, bb[j], acc[1][j]);
                }
            }

#pragma unroll
            for (int i = 0; i < 2; i++) {
                float  e[8];
                double rs = 0.0;
#pragma unroll
                for (int j = 0; j < 8; j++) {
                    float sc = acc[i][j] * 0.125f + 1.0f;
                    e[j] = expf(sc);
                    rs += (double)e[j];
                }
                int rowi = ty * 2 + i;
                *(float4*)&Es[rowi*512 + kt*128 + tx*8]     = make_float4(e[0], e[1], e[2], e[3]);
                *(float4*)&Es[rowi*512 + kt*128 + tx*8 + 4] = make_float4(e[4], e[5], e[6], e[7]);
                rs += __shfl_xor_sync(0xffffffffu, rs, 8);
                rs += __shfl_xor_sync(0xffffffffu, rs, 4);
                rs += __shfl_xor_sync(0xffffffffu, rs, 2);
                rs += __shfl_xor_sync(0xffffffffu, rs, 1);
                if (tx == 0) denom[rowi] += rs;
            }
            __syncthreads();
        }

        if (t < 32) invd[t] = 1.0 / denom[t];
        __syncthreads();

#pragma unroll
        for (int ss = 0; ss < 2; ss++) {
            int s = t + ss * 256;
            double a = colacc[s];
#pragma unroll 8
            for (int rr = 0; rr < 32; rr++)
                a = fma((double)Es[rr*512 + s], invd[rr], a);
            colacc[s] = a;
        }
    }

    g_colpart[(size_t)bh * TS + t]       = colacc[t];
    g_colpart[(size_t)bh * TS + t + 256] = colacc[t + 256];
}

// ---------------------------------------------------------------------------
// col -> log_softmax logits (fp64, deterministic tree reductions)
// ---------------------------------------------------------------------------
__global__ __launch_bounds__(512) void logits_kernel()
{
    __shared__ double red[512];
    const int b = blockIdx.x;
    const int s = threadIdx.x;

    double v = 0.0;
#pragma unroll
    for (int h = 0; h < TH; h++)
        v += g_colpart[((size_t)b * TH + h) * TS + s];

    red[s] = v;
    __syncthreads();
    for (int off = 256; off > 0; off >>= 1) {
        if (s < off) { double o = red[s + off]; if (o > red[s]) red[s] = o; }
        __syncthreads();
    }
    double m = red[0];
    __syncthreads();
    red[s] = exp(v - m);
    __syncthreads();
    for (int off = 256; off > 0; off >>= 1) {
        if (s < off) red[s] += red[s + off];
        __syncthreads();
    }
    double lse = m + log(red[0]);
    g_logits[(size_t)b * TS + s] = v - lse;
}

// ---------------------------------------------------------------------------
// Threefry-2x32 (JAX-exact, PARTITIONABLE): bits = o0 ^ o1, counter (0, i)
// ---------------------------------------------------------------------------
__device__ __forceinline__ void threefry2x32(
    unsigned k0, unsigned k1, unsigned x0, unsigned x1,
    unsigned& o0, unsigned& o1)
{
    const unsigned ks0 = k0, ks1 = k1, ks2 = k0 ^ k1 ^ 0x1BD11BDAu;
    x0 += ks0; x1 += ks1;
#define TF_RND(r) { x0 += x1; x1 = __funnelshift_l(x1, x1, r); x1 ^= x0; }
    TF_RND(13) TF_RND(15) TF_RND(26) TF_RND(6)   x0 += ks1; x1 += ks2 + 1u;
    TF_RND(17) TF_RND(29) TF_RND(16) TF_RND(24)  x0 += ks2; x1 += ks0 + 2u;
    TF_RND(13) TF_RND(15) TF_RND(26) TF_RND(6)   x0 += ks0; x1 += ks1 + 3u;
    TF_RND(17) TF_RND(29) TF_RND(16) TF_RND(24)  x0 += ks1; x1 += ks2 + 4u;
    TF_RND(13) TF_RND(15) TF_RND(26) TF_RND(6)   x0 += ks2; x1 += ks0 + 5u;
#undef TF_RND
    o0 = x0; o1 = x1;
}

// ---------------------------------------------------------------------------
// sample_kernel v2 (validated in round 9): fp32 fast path + selective fp64
// verification; selected index provably identical to the all-fp64 kernel.
// ---------------------------------------------------------------------------
__global__ __launch_bounds__(256) void sample_kernel(
    const float* __restrict__ tokens, float* __restrict__ out)
{
    const int warp = blockIdx.x * 8 + (threadIdx.x >> 5);   // 0..16383 = b*1024+j
    const int lane = threadIdx.x & 31;
    const int b = warp >> 10;
    const int j = warp & 1023;

    const double* lg = g_logits + (size_t)b * TS;

    float vreg[16];
    float best32 = -3.0e38f;
#pragma unroll
    for (int si = 0; si < 16; si++) {
        int s = lane + si * 32;
        unsigned i = (unsigned)warp * 512u + (unsigned)s;
        unsigned o0, o1;
        threefry2x32(0u, 42u, 0u, i, o0, o1);
        unsigned bits = o0 ^ o1;
        float f = __uint_as_float((bits >> 9) | 0x3f800000u) - 1.0f;
        float u = fmaxf(f, 1.17549435e-38f);
        float g32 = -logf(-logf(u));
        float v32 = g32 + (float)lg[s];
        vreg[si] = v32;
        best32 = fmaxf(best32, v32);
    }
#pragma unroll
    for (int off = 16; off > 0; off >>= 1)
        best32 = fmaxf(best32, __shfl_xor_sync(0xffffffffu, best32, off));

    const float thresh = best32 - 1.0e-4f;
    double best = -1.0e300;
    int    bi   = 0x7fffffff;
#pragma unroll
    for (int si = 0; si < 16; si++) {
        if (vreg[si] >= thresh) {
            int s = lane + si * 32;
            unsigned i = (unsigned)warp * 512u + (unsigned)s;
            unsigned o0, o1;
            threefry2x32(0u, 42u, 0u, i, o0, o1);
            unsigned bits = o0 ^ o1;
            float f = __uint_as_float((bits >> 9) | 0x3f800000u) - 1.0f;
            float u = fmaxf(f, 1.17549435e-38f);
            double g = -log(-log((double)u));        // EXACT round-3..9 formula
            double v = g + lg[s];
            if (v > best) { best = v; bi = s; }
        }
    }

#pragma unroll
    for (int off = 16; off > 0; off >>= 1) {
        double ov = __shfl_down_sync(0xffffffffu, best, off);
        int    oi = __shfl_down_sync(0xffffffffu, bi,   off);
        if (ov > best || (ov == best && oi < bi)) { best = ov; bi = oi; }
    }

    if (lane == 0)
        out[warp] = tokens[((size_t)b * TS + (size_t)bi) * TE + (size_t)j];
}

// ---------------------------------------------------------------------------
extern "C" void kernel_launch(void* const* d_in, const int* in_sizes, int n_in,
                              void* d_out, int out_size)
{
    (void)in_sizes; (void)n_in; (void)out_size;
    const float* tokens = (const float*)d_in[0];
    const float* Wq     = (const float*)d_in[1];
    const float* bq     = (const float*)d_in[2];
    const float* Wk     = (const float*)d_in[3];
    const float* bk     = (const float*)d_in[4];
    float* out = (float*)d_out;

    cudaFuncSetAttribute(gemm_hmma_kernel,
                         cudaFuncAttributeMaxDynamicSharedMemorySize, GEMM_SMEM);
    cudaFuncSetAttribute(attn_col_kernel,
                         cudaFuncAttributeMaxDynamicSharedMemorySize, ATTN_SMEM);

    split_tokens_kernel<<<8192, 256>>>(tokens);
    split_w_kernel<<<dim3(1024, 1, 2), 256>>>(Wq, Wk);
    gemm_hmma_kernel<<<dim3(8, 64, 2), 256, GEMM_SMEM>>>(bq, bk);
    attn_col_kernel<<<256, 256, ATTN_SMEM>>>();
    logits_kernel<<<16, 512>>>();
    sample_kernel<<<2048, 256>>>(tokens, out);
}

// round 11
// speedup vs baseline: 1.1431x; 1.1431x over previous
#include <cuda_runtime.h>
#include <cuda_bf16.h>
#include <math.h>
#include <stdint.h>

#define TB 16
#define TS 512
#define TE 1024
#define TH 16
#define TD 64
#define KSPLIT 3072          // 3 * TE (bf16 hi|mid|lo splits along K)

// Scratch (device globals: allocation-free rule)
static __device__ float  g_Q[(size_t)TB * TS * TE];
static __device__ float  g_K[(size_t)TB * TS * TE];
static __device__ double g_colpart[TB * TH * TS];
static __device__ double g_logits[TB * TS];
static __device__ __align__(128) __nv_bfloat16 g_As[(size_t)TB * TS * KSPLIT]; // tokens split
static __device__ __align__(128) __nv_bfloat16 g_Ws[(size_t)2 * TE * KSPLIT];  // Wq/Wk split
// per-head bf16 splits of Q/K: [bh][512 rows][3 segs x 64] (row = 192 bf16)
static __device__ __align__(128) __nv_bfloat16 g_Qs2[(size_t)TB * TH * TS * 192];
static __device__ __align__(128) __nv_bfloat16 g_Ks2[(size_t)TB * TH * TS * 192];

// ---------------------------------------------------------------------------
// PTX helpers (sm_80-class only: mma.sync / ldmatrix / cp.async — NO tcgen05)
// ---------------------------------------------------------------------------
__device__ __forceinline__ uint32_t smem_u32(const void* p) {
    uint32_t a;
    asm("{ .reg .u64 t; cvta.to.shared.u64 t, %1; cvt.u32.u64 %0, t; }" : "=r"(a) : "l"(p));
    return a;
}
#define SW128(o) ((o) ^ ((((uint32_t)(o)) >> 3) & 0x70u))

#define CP_ASYNC16(dst, src) \
    asm volatile("cp.async.cg.shared.global [%0], [%1], 16;" :: "r"(dst), "l"(src))
#define CP_COMMIT()  asm volatile("cp.async.commit_group;" ::: "memory")
#define CP_WAIT1()   asm volatile("cp.async.wait_group 1;" ::: "memory")
#define CP_WAIT0()   asm volatile("cp.async.wait_group 0;" ::: "memory")

#define LDSM_X4(r0, r1, r2, r3, a) \
    asm volatile("ldmatrix.sync.aligned.m8n8.x4.shared.b16 {%0,%1,%2,%3}, [%4];" \
                 : "=r"(r0), "=r"(r1), "=r"(r2), "=r"(r3) : "r"(a))

#define MMA_16816(D, A, B0, B1) \
    asm volatile("mma.sync.aligned.m16n8k16.row.col.f32.bf16.bf16.f32 " \
                 "{%0,%1,%2,%3}, {%4,%5,%6,%7}, {%8,%9}, {%0,%1,%2,%3};" \
                 : "+f"((D)[0]), "+f"((D)[1]), "+f"((D)[2]), "+f"((D)[3]) \
                 : "r"((A)[0]), "r"((A)[1]), "r"((A)[2]), "r"((A)[3]), \
                   "r"(B0), "r"(B1))

// ---------------------------------------------------------------------------
// Exact 3-way bf16 split
// ---------------------------------------------------------------------------
__device__ __forceinline__ void split3(float x, unsigned short& h, unsigned short& m,
                                       unsigned short& l) {
    __nv_bfloat16 bh = __float2bfloat16_rn(x);
    float r  = x - __bfloat162float(bh);
    __nv_bfloat16 bm = __float2bfloat16_rn(r);
    float r2 = r - __bfloat162float(bm);
    __nv_bfloat16 bl = __float2bfloat16_rn(r2);
    h = __bfloat16_as_ushort(bh);
    m = __bfloat16_as_ushort(bm);
    l = __bfloat16_as_ushort(bl);
}

__device__ __forceinline__ void split_store4s(const float4 v, __nv_bfloat16* dst, int stride) {
    unsigned short h[4], m[4], l[4];
    split3(v.x, h[0], m[0], l[0]);
    split3(v.y, h[1], m[1], l[1]);
    split3(v.z, h[2], m[2], l[2]);
    split3(v.w, h[3], m[3], l[3]);
    uint2 uh = make_uint2((uint32_t)h[0] | ((uint32_t)h[1] << 16),
                          (uint32_t)h[2] | ((uint32_t)h[3] << 16));
    uint2 um = make_uint2((uint32_t)m[0] | ((uint32_t)m[1] << 16),
                          (uint32_t)m[2] | ((uint32_t)m[3] << 16));
    uint2 ul = make_uint2((uint32_t)l[0] | ((uint32_t)l[1] << 16),
                          (uint32_t)l[2] | ((uint32_t)l[3] << 16));
    *(uint2*)(dst)              = uh;
    *(uint2*)(dst + stride)     = um;
    *(uint2*)(dst + 2 * stride) = ul;
}

// tokens [8192,1024] fp32 -> g_As [8192, 3072] bf16 (hi|mid|lo thirds)
__global__ __launch_bounds__(256) void split_tokens_kernel(const float* __restrict__ x)
{
    size_t i = (size_t)blockIdx.x * 256 + threadIdx.x;     // float4 index
    float4 v = ((const float4*)x)[i];
    size_t row = i >> 8;
    int    c4  = (int)(i & 255) * 4;
    split_store4s(v, g_As + row * KSPLIT + c4, TE);
}

// Wq/Wk [1024,1024] fp32 -> g_Ws [2][1024, 3072] bf16
__global__ __launch_bounds__(256) void split_w_kernel(const float* __restrict__ Wq,
                                                      const float* __restrict__ Wk)
{
    const float* W = (blockIdx.z == 0) ? Wq : Wk;
    size_t i = (size_t)blockIdx.x * 256 + threadIdx.x;
    float4 v = ((const float4*)W)[i];
    size_t row = i >> 8;
    int    c4  = (int)(i & 255) * 4;
    split_store4s(v, g_Ws + (size_t)blockIdx.z * TE * KSPLIT + row * KSPLIT + c4, TE);
}

// g_Q/g_K fp32 [8192,1024] -> per-head split [bh][512][3*64] bf16
__global__ __launch_bounds__(256) void split_qk_kernel()
{
    const float*    src = blockIdx.z ? g_K : g_Q;
    __nv_bfloat16*  dst = blockIdx.z ? g_Ks2 : g_Qs2;
    size_t i = (size_t)blockIdx.x * 256 + threadIdx.x;     // float4 idx (2,097,152)
    float4 v = ((const float4*)src)[i];
    size_t r = i >> 8;
    int    c4 = (int)(i & 255) * 4;
    int h = c4 >> 6, d = c4 & 63;
    int b = (int)(r >> 9), s = (int)(r & 511);
    __nv_bfloat16* o = dst + (((size_t)(b * TH + h) * TS + s) * 192 + d);
    split_store4s(v, o, 64);
}

// ---------------------------------------------------------------------------
// HMMA GEMM (validated): 6-term bf16-split product
// ---------------------------------------------------------------------------
#define GEMM_STAGES 3
#define GEMM_STAGE_BYTES 32768
#define GEMM_SMEM (GEMM_STAGES * GEMM_STAGE_BYTES)
#define NCHUNK 96

__global__ __launch_bounds__(256) void gemm_hmma_kernel(const float* __restrict__ bq,
                                                        const float* __restrict__ bk)
{
    extern __shared__ char dsm[];
    const uint32_t smem_base = smem_u32(dsm);

    const int t    = threadIdx.x;
    const int lane = t & 31, wid = t >> 5;
    const int warp_m = wid & 3;
    const int warp_n = wid >> 2;
    const int sel = blockIdx.z;
    const int m0  = blockIdx.y * 128;
    const int n0  = blockIdx.x * 128;

    float*       C    = sel ? g_K : g_Q;
    const float* bias = sel ? bk : bq;

    const int row  = t >> 1;
    const int half = t & 1;
    const char* aG = (const char*)(g_As + (size_t)(m0 + row) * KSPLIT + half * 32);
    const char* bG = (const char*)(g_Ws + (size_t)sel * TE * KSPLIT
                                        + (size_t)(n0 + row) * KSPLIT + half * 32);
    uint32_t dOffA[4], dOffB[4];
#pragma unroll
    for (int i = 0; i < 4; i++) {
        uint32_t o = SW128((uint32_t)(row * 128 + half * 64 + i * 16));
        dOffA[i] = o;
        dOffB[i] = 16384u + o;
    }
    const uint32_t segA = 0x0010210u;   // [0,1,2,0,1,0]
    const uint32_t segB = 0x0211000u;   // [0,0,0,1,1,2]

#define ISSUE_STAGE(c_) do {                                                   \
    int _c = (c_);                                                             \
    int _seg = _c >> 4, _kc = _c & 15;                                         \
    int _pa = (segA >> (_seg * 4)) & 7, _pb = (segB >> (_seg * 4)) & 7;        \
    uint32_t _sb = smem_base + (_c % GEMM_STAGES) * GEMM_STAGE_BYTES;          \
    const char* _as = aG + (_pa * 1024 + _kc * 64) * 2;                        \
    const char* _bs = bG + (_pb * 1024 + _kc * 64) * 2;                        \
    _Pragma("unroll")                                                          \
    for (int _i = 0; _i < 4; _i++) {                                           \
        CP_ASYNC16(_sb + dOffA[_i], _as + _i * 16);                            \
        CP_ASYNC16(_sb + dOffB[_i], _bs + _i * 16);                            \
    }                                                                          \
    CP_COMMIT();                                                               \
} while (0)

    float acc[2][8][4];
#pragma unroll
    for (int i = 0; i < 2; i++)
#pragma unroll
        for (int j = 0; j < 8; j++)
#pragma unroll
            for (int k = 0; k < 4; k++) acc[i][j][k] = 0.f;

    const uint32_t lrow = lane & 15;
    const uint32_t lcol = (lane >> 4) * 16;

    ISSUE_STAGE(0);
    ISSUE_STAGE(1);

    for (int c = 0; c < NCHUNK; c++) {
        if (c < NCHUNK - 1) CP_WAIT1(); else CP_WAIT0();
        __syncthreads();
        if (c + 2 < NCHUNK) ISSUE_STAGE(c + 2);

        const uint32_t sb  = smem_base + (c % GEMM_STAGES) * GEMM_STAGE_BYTES;
        const uint32_t aRow = (uint32_t)(warp_m * 32) + lrow;
        const uint32_t bRow = (uint32_t)(warp_n * 64) + lrow;

#pragma unroll
        for (int kk = 0; kk < 4; kk++) {
            uint32_t a[2][4];
#pragma unroll
            for (int mt = 0; mt < 2; mt++) {
                uint32_t off = (aRow + mt * 16) * 128 + kk * 32 + lcol;
                LDSM_X4(a[mt][0], a[mt][1], a[mt][2], a[mt][3], sb + SW128(off));
            }
            uint32_t b[4][4];
#pragma unroll
            for (int nt2 = 0; nt2 < 4; nt2++) {
                uint32_t off = (bRow + nt2 * 16) * 128 + kk * 32 + lcol;
                LDSM_X4(b[nt2][0], b[nt2][1], b[nt2][2], b[nt2][3],
                        sb + 16384u + SW128(off));
            }
#pragma unroll
            for (int mt = 0; mt < 2; mt++)
#pragma unroll
                for (int nt2 = 0; nt2 < 4; nt2++) {
                    MMA_16816(acc[mt][nt2 * 2 + 0], a[mt], b[nt2][0], b[nt2][2]);
                    MMA_16816(acc[mt][nt2 * 2 + 1], a[mt], b[nt2][1], b[nt2][3]);
                }
        }
    }

    const int er = lane >> 2;
    const int ec = (lane & 3) * 2;
#pragma unroll
    for (int mt = 0; mt < 2; mt++) {
        const int r0 = m0 + warp_m * 32 + mt * 16 + er;
#pragma unroll
        for (int nt = 0; nt < 8; nt++) {
            const int col = n0 + warp_n * 64 + nt * 8 + ec;
            const float bx = bias[col], by = bias[col + 1];
            float* p = C + (size_t)r0 * TE + col;
            *(float2*)p            = make_float2(acc[mt][nt][0] + bx, acc[mt][nt][1] + by);
            *(float2*)(p + 8 * TE) = make_float2(acc[mt][nt][2] + bx, acc[mt][nt][3] + by);
        }
    }
#undef ISSUE_STAGE
}

// ---------------------------------------------------------------------------
// Attention-column kernel v4: HMMA scores.
// One block per (b,h); 8 warps: warp_m = wid&3 (16 rows), warp_n = wid>>2
// (64 of 128 cols). Scores via 6-term bf16-split MMA (exact to ~2^-24).
// Es rows padded to 514 floats to spread banks. Denominators: quad-shfl
// fp64 sums -> den2[row][warp_n] single-writer. colacc fp64 as before.
// ---------------------------------------------------------------------------
#define ES_STRIDE 514
#define OFF_QS  (64 * ES_STRIDE * 4)             // 131584
#define OFF_KS  (OFF_QS + 3 * 8192)              // +24576
#define OFF_COL (OFF_KS + 3 * 16384)             // +49152
#define OFF_DEN (OFF_COL + 512 * 8)
#define OFF_INV (OFF_DEN + 128 * 8)
#define ATTN_SMEM (OFF_INV + 64 * 8)

__global__ __launch_bounds__(256) void attn_col_kernel()
{
    extern __shared__ char sm[];
    const uint32_t sb = smem_u32(sm);
    float*  Es     = (float*)sm;
    double* colacc = (double*)(sm + OFF_COL);
    double* den2   = (double*)(sm + OFF_DEN);    // [64][2]
    double* invd   = (double*)(sm + OFF_INV);    // [64]

    const int t = threadIdx.x, lane = t & 31, wid = t >> 5;
    const int wm = wid & 3, wn = wid >> 2;
    const int bh = blockIdx.x;

    const __nv_bfloat16* Qg = g_Qs2 + (size_t)bh * TS * 192;
    const __nv_bfloat16* Kg = g_Ks2 + (size_t)bh * TS * 192;

    colacc[t] = 0.0;
    colacc[t + 256] = 0.0;

    const uint32_t lrow = lane & 15;
    const uint32_t lcol = (lane >> 4) * 16;
    const int fr = lane >> 2;                     // fragment row within 8
    const int fc = (lane & 3) * 2;                // fragment col pair
    const int segAa[6] = {0, 1, 2, 0, 1, 0};
    const int segBa[6] = {0, 0, 0, 1, 1, 2};

    for (int qt = 0; qt < 8; qt++) {
        __syncthreads();   // colacc reads of prev Es done; prev ldsm done
        // load Q tile planes: 64 rows x 384B -> 3 SW128 planes (8KB each)
        {
            int row = t >> 2, qq = t & 3;
            const char* src = (const char*)(Qg + (size_t)(qt * 64 + row) * 192) + qq * 96;
#pragma unroll
            for (int j = 0; j < 6; j++) {
                int i = qq * 6 + j;
                int seg = i >> 3, wi = (i & 7) * 16;
                CP_ASYNC16(sb + OFF_QS + seg * 8192 + SW128(row * 128 + wi), src + j * 16);
            }
        }
        CP_COMMIT();
        if (t < 128) den2[t] = 0.0;

        for (int kt = 0; kt < 4; kt++) {
            __syncthreads();   // prev stage's ldsm reads of Ks done
            // load K tile planes: 128 rows x 384B -> 3 SW128 planes (16KB each)
            {
                int row = t >> 1, hf = t & 1;
                const char* src = (const char*)(Kg + (size_t)(kt * 128 + row) * 192) + hf * 192;
#pragma unroll
                for (int j = 0; j < 12; j++) {
                    int i = hf * 12 + j;
                    int seg = i >> 3, wi = (i & 7) * 16;
                    CP_ASYNC16(sb + OFF_KS + seg * 16384 + SW128(row * 128 + wi), src + j * 16);
                }
            }
            CP_COMMIT();
            CP_WAIT0();
            __syncthreads();

            float acc[8][4];
#pragma unroll
            for (int i = 0; i < 8; i++)
#pragma unroll
                for (int k = 0; k < 4; k++) acc[i][k] = 0.f;

#pragma unroll
            for (int ch = 0; ch < 6; ch++) {
                const uint32_t abase = sb + OFF_QS + segAa[ch] * 8192;
                const uint32_t bbase = sb + OFF_KS + segBa[ch] * 16384;
#pragma unroll
                for (int kk = 0; kk < 4; kk++) {
                    uint32_t a[4];
                    LDSM_X4(a[0], a[1], a[2], a[3],
                            abase + SW128((wm * 16 + lrow) * 128 + kk * 32 + lcol));
                    uint32_t b[4][4];
#pragma unroll
                    for (int nt2 = 0; nt2 < 4; nt2++)
                        LDSM_X4(b[nt2][0], b[nt2][1], b[nt2][2], b[nt2][3],
                                bbase + SW128((wn * 64 + nt2 * 16 + lrow) * 128 + kk * 32 + lcol));
#pragma unroll
                    for (int nt2 = 0; nt2 < 4; nt2++) {
                        MMA_16816(acc[nt2 * 2 + 0], a, b[nt2][0], b[nt2][2]);
                        MMA_16816(acc[nt2 * 2 + 1], a, b[nt2][1], b[nt2][3]);
                    }
                }
            }

            // epilogue: exp, Es stores, fp64 row sums
            const int r0 = wm * 16 + fr;          // rows r0, r0+8
            double d0 = 0.0, d1 = 0.0;
#pragma unroll
            for (int nt = 0; nt < 8; nt++) {
                const int col = kt * 128 + wn * 64 + nt * 8 + fc;
                float e0 = expf(acc[nt][0] * 0.125f + 1.0f);
                float e1 = expf(acc[nt][1] * 0.125f + 1.0f);
                float e2 = expf(acc[nt][2] * 0.125f + 1.0f);
                float e3 = expf(acc[nt][3] * 0.125f + 1.0f);
                *(float2*)&Es[r0 * ES_STRIDE + col]       = make_float2(e0, e1);
                *(float2*)&Es[(r0 + 8) * ES_STRIDE + col] = make_float2(e2, e3);
                d0 += (double)e0 + (double)e1;
                d1 += (double)e2 + (double)e3;
            }
            d0 += __shfl_xor_sync(0xffffffffu, d0, 1);
            d0 += __shfl_xor_sync(0xffffffffu, d0, 2);
            d1 += __shfl_xor_sync(0xffffffffu, d1, 1);
            d1 += __shfl_xor_sync(0xffffffffu, d1, 2);
            if ((lane & 3) == 0) {
                den2[r0 * 2 + wn]       += d0;
                den2[(r0 + 8) * 2 + wn] += d1;
            }
        }

        __syncthreads();
        if (t < 64) invd[t] = 1.0 / (den2[t * 2] + den2[t * 2 + 1]);
        __syncthreads();

#pragma unroll
        for (int ss = 0; ss < 2; ss++) {
            int s = t + ss * 256;
            double a = colacc[s];
#pragma unroll 8
            for (int rr = 0; rr < 64; rr++)
                a = fma((double)Es[rr * ES_STRIDE + s], invd[rr], a);
            colacc[s] = a;
        }
    }

    g_colpart[(size_t)bh * TS + t]       = colacc[t];
    g_colpart[(size_t)bh * TS + t + 256] = colacc[t + 256];
}

// ---------------------------------------------------------------------------
// col -> log_softmax logits (fp64, deterministic tree reductions)
// ---------------------------------------------------------------------------
__global__ __launch_bounds__(512) void logits_kernel()
{
    __shared__ double red[512];
    const int b = blockIdx.x;
    const int s = threadIdx.x;

    double v = 0.0;
#pragma unroll
    for (int h = 0; h < TH; h++)
        v += g_colpart[((size_t)b * TH + h) * TS + s];

    red[s] = v;
    __syncthreads();
    for (int off = 256; off > 0; off >>= 1) {
        if (s < off) { double o = red[s + off]; if (o > red[s]) red[s] = o; }
        __syncthreads();
    }
    double m = red[0];
    __syncthreads();
    red[s] = exp(v - m);
    __syncthreads();
    for (int off = 256; off > 0; off >>= 1) {
        if (s < off) red[s] += red[s + off];
        __syncthreads();
    }
    double lse = m + log(red[0]);
    g_logits[(size_t)b * TS + s] = v - lse;
}

// ---------------------------------------------------------------------------
// Threefry-2x32 (JAX-exact, PARTITIONABLE): bits = o0 ^ o1, counter (0, i)
// ---------------------------------------------------------------------------
__device__ __forceinline__ void threefry2x32(
    unsigned k0, unsigned k1, unsigned x0, unsigned x1,
    unsigned& o0, unsigned& o1)
{
    const unsigned ks0 = k0, ks1 = k1, ks2 = k0 ^ k1 ^ 0x1BD11BDAu;
    x0 += ks0; x1 += ks1;
#define TF_RND(r) { x0 += x1; x1 = __funnelshift_l(x1, x1, r); x1 ^= x0; }
    TF_RND(13) TF_RND(15) TF_RND(26) TF_RND(6)   x0 += ks1; x1 += ks2 + 1u;
    TF_RND(17) TF_RND(29) TF_RND(16) TF_RND(24)  x0 += ks2; x1 += ks0 + 2u;
    TF_RND(13) TF_RND(15) TF_RND(26) TF_RND(6)   x0 += ks0; x1 += ks1 + 3u;
    TF_RND(17) TF_RND(29) TF_RND(16) TF_RND(24)  x0 += ks1; x1 += ks2 + 4u;
    TF_RND(13) TF_RND(15) TF_RND(26) TF_RND(6)   x0 += ks2; x1 += ks0 + 5u;
#undef TF_RND
    o0 = x0; o1 = x1;
}

// ---------------------------------------------------------------------------
// sample_kernel (validated R9): fp32 fast path + selective fp64 verification
// ---------------------------------------------------------------------------
__global__ __launch_bounds__(256) void sample_kernel(
    const float* __restrict__ tokens, float* __restrict__ out)
{
    const int warp = blockIdx.x * 8 + (threadIdx.x >> 5);   // 0..16383 = b*1024+j
    const int lane = threadIdx.x & 31;
    const int b = warp >> 10;
    const int j = warp & 1023;

    const double* lg = g_logits + (size_t)b * TS;

    float vreg[16];
    float best32 = -3.0e38f;
#pragma unroll
    for (int si = 0; si < 16; si++) {
        int s = lane + si * 32;
        unsigned i = (unsigned)warp * 512u + (unsigned)s;
        unsigned o0, o1;
        threefry2x32(0u, 42u, 0u, i, o0, o1);
        unsigned bits = o0 ^ o1;
        float f = __uint_as_float((bits >> 9) | 0x3f800000u) - 1.0f;
        float u = fmaxf(f, 1.17549435e-38f);
        float g32 = -logf(-logf(u));
        float v32 = g32 + (float)lg[s];
        vreg[si] = v32;
        best32 = fmaxf(best32, v32);
    }
#pragma unroll
    for (int off = 16; off > 0; off >>= 1)
        best32 = fmaxf(best32, __shfl_xor_sync(0xffffffffu, best32, off));

    const float thresh = best32 - 1.0e-4f;
    double best = -1.0e300;
    int    bi   = 0x7fffffff;
#pragma unroll
    for (int si = 0; si < 16; si++) {
        if (vreg[si] >= thresh) {
            int s = lane + si * 32;
            unsigned i = (unsigned)warp * 512u + (unsigned)s;
            unsigned o0, o1;
            threefry2x32(0u, 42u, 0u, i, o0, o1);
            unsigned bits = o0 ^ o1;
            float f = __uint_as_float((bits >> 9) | 0x3f800000u) - 1.0f;
            float u = fmaxf(f, 1.17549435e-38f);
            double g = -log(-log((double)u));        // EXACT round-3..10 formula
            double v = g + lg[s];
            if (v > best) { best = v; bi = s; }
        }
    }

#pragma unroll
    for (int off = 16; off > 0; off >>= 1) {
        double ov = __shfl_down_sync(0xffffffffu, best, off);
        int    oi = __shfl_down_sync(0xffffffffu, bi,   off);
        if (ov > best || (ov == best && oi < bi)) { best = ov; bi = oi; }
    }

    if (lane == 0)
        out[warp] = tokens[((size_t)b * TS + (size_t)bi) * TE + (size_t)j];
}

// ---------------------------------------------------------------------------
extern "C" void kernel_launch(void* const* d_in, const int* in_sizes, int n_in,
                              void* d_out, int out_size)
{
    (void)in_sizes; (void)n_in; (void)out_size;
    const float* tokens = (const float*)d_in[0];
    const float* Wq     = (const float*)d_in[1];
    const float* bq     = (const float*)d_in[2];
    const float* Wk     = (const float*)d_in[3];
    const float* bk     = (const float*)d_in[4];
    float* out = (float*)d_out;

    cudaFuncSetAttribute(gemm_hmma_kernel,
                         cudaFuncAttributeMaxDynamicSharedMemorySize, GEMM_SMEM);
    cudaFuncSetAttribute(attn_col_kernel,
                         cudaFuncAttributeMaxDynamicSharedMemorySize, ATTN_SMEM);

    split_tokens_kernel<<<8192, 256>>>(tokens);
    split_w_kernel<<<dim3(1024, 1, 2), 256>>>(Wq, Wk);
    gemm_hmma_kernel<<<dim3(8, 64, 2), 256, GEMM_SMEM>>>(bq, bk);
    split_qk_kernel<<<dim3(8192, 1, 2), 256>>>();
    attn_col_kernel<<<256, 256, ATTN_SMEM>>>();
    logits_kernel<<<16, 512>>>();
    sample_kernel<<<2048, 256>>>(tokens, out);
}

// round 12
// speedup vs baseline: 1.1444x; 1.0012x over previous
#include <cuda_runtime.h>
#include <cuda_bf16.h>
#include <math.h>
#include <stdint.h>

#define TB 16
#define TS 512
#define TE 1024
#define TH 16
#define TD 64
#define KSPLIT 3072          // 3 * TE (bf16 hi|mid|lo splits along K)

// Scratch (device globals: allocation-free rule)
static __device__ float  g_Q[(size_t)TB * TS * TE];
static __device__ float  g_K[(size_t)TB * TS * TE];
static __device__ double g_colpart[TB * TH * TS];
static __device__ double g_logits[TB * TS];
static __device__ __align__(128) __nv_bfloat16 g_As[(size_t)TB * TS * KSPLIT]; // tokens split
static __device__ __align__(128) __nv_bfloat16 g_Ws[(size_t)2 * TE * KSPLIT];  // Wq/Wk split
// per-head bf16 splits of Q/K: [bh][512 rows][3 segs x 64] (row = 192 bf16)
static __device__ __align__(128) __nv_bfloat16 g_Qs2[(size_t)TB * TH * TS * 192];
static __device__ __align__(128) __nv_bfloat16 g_Ks2[(size_t)TB * TH * TS * 192];

// ---------------------------------------------------------------------------
// PTX helpers (sm_80-class only: mma.sync / ldmatrix / cp.async — NO tcgen05)
// ---------------------------------------------------------------------------
__device__ __forceinline__ uint32_t smem_u32(const void* p) {
    uint32_t a;
    asm("{ .reg .u64 t; cvta.to.shared.u64 t, %1; cvt.u32.u64 %0, t; }" : "=r"(a) : "l"(p));
    return a;
}
#define SW128(o) ((o) ^ ((((uint32_t)(o)) >> 3) & 0x70u))

#define CP_ASYNC16(dst, src) \
    asm volatile("cp.async.cg.shared.global [%0], [%1], 16;" :: "r"(dst), "l"(src))
#define CP_COMMIT()  asm volatile("cp.async.commit_group;" ::: "memory")
#define CP_WAIT1()   asm volatile("cp.async.wait_group 1;" ::: "memory")
#define CP_WAIT0()   asm volatile("cp.async.wait_group 0;" ::: "memory")

#define LDSM_X4(r0, r1, r2, r3, a) \
    asm volatile("ldmatrix.sync.aligned.m8n8.x4.shared.b16 {%0,%1,%2,%3}, [%4];" \
                 : "=r"(r0), "=r"(r1), "=r"(r2), "=r"(r3) : "r"(a))

#define MMA_16816(D, A, B0, B1) \
    asm volatile("mma.sync.aligned.m16n8k16.row.col.f32.bf16.bf16.f32 " \
                 "{%0,%1,%2,%3}, {%4,%5,%6,%7}, {%8,%9}, {%0,%1,%2,%3};" \
                 : "+f"((D)[0]), "+f"((D)[1]), "+f"((D)[2]), "+f"((D)[3]) \
                 : "r"((A)[0]), "r"((A)[1]), "r"((A)[2]), "r"((A)[3]), \
                   "r"(B0), "r"(B1))

// ---------------------------------------------------------------------------
// Deterministic FMA-pipe exp (replaces MUFU-bound expf in the hot epilogue).
// Cody-Waite range reduction + degree-7 Taylor; rel err ~5e-9 + reduction
// ~1e-10 — same noise class as fp32 rounding (washed; proven in R3).
// ---------------------------------------------------------------------------
__device__ __forceinline__ float fast_expf(float x) {
    const float LOG2E   = 1.4426950408889634f;
    const float LN2_HI  = 0.693145751953125f;
    const float LN2_LO  = 1.428606765330187e-06f;
    float y  = x * LOG2E;
    float r  = rintf(y);
    int   ri = (int)r;
    float t  = fmaf(-r, LN2_HI, x);
    t = fmaf(-r, LN2_LO, t);
    float p = 1.9841269841e-4f;          // 1/5040
    p = fmaf(p, t, 1.3888888889e-3f);    // 1/720
    p = fmaf(p, t, 8.3333333333e-3f);    // 1/120
    p = fmaf(p, t, 4.1666666667e-2f);    // 1/24
    p = fmaf(p, t, 1.6666666667e-1f);    // 1/6
    p = fmaf(p, t, 0.5f);
    p = fmaf(p, t, 1.0f);
    p = fmaf(p, t, 1.0f);
    return p * __int_as_float((ri + 127) << 23);
}

// ---------------------------------------------------------------------------
// Exact 3-way bf16 split
// ---------------------------------------------------------------------------
__device__ __forceinline__ void split3(float x, unsigned short& h, unsigned short& m,
                                       unsigned short& l) {
    __nv_bfloat16 bh = __float2bfloat16_rn(x);
    float r  = x - __bfloat162float(bh);
    __nv_bfloat16 bm = __float2bfloat16_rn(r);
    float r2 = r - __bfloat162float(bm);
    __nv_bfloat16 bl = __float2bfloat16_rn(r2);
    h = __bfloat16_as_ushort(bh);
    m = __bfloat16_as_ushort(bm);
    l = __bfloat16_as_ushort(bl);
}

__device__ __forceinline__ void split_store4s(const float4 v, __nv_bfloat16* dst, int stride) {
    unsigned short h[4], m[4], l[4];
    split3(v.x, h[0], m[0], l[0]);
    split3(v.y, h[1], m[1], l[1]);
    split3(v.z, h[2], m[2], l[2]);
    split3(v.w, h[3], m[3], l[3]);
    uint2 uh = make_uint2((uint32_t)h[0] | ((uint32_t)h[1] << 16),
                          (uint32_t)h[2] | ((uint32_t)h[3] << 16));
    uint2 um = make_uint2((uint32_t)m[0] | ((uint32_t)m[1] << 16),
                          (uint32_t)m[2] | ((uint32_t)m[3] << 16));
    uint2 ul = make_uint2((uint32_t)l[0] | ((uint32_t)l[1] << 16),
                          (uint32_t)l[2] | ((uint32_t)l[3] << 16));
    *(uint2*)(dst)              = uh;
    *(uint2*)(dst + stride)     = um;
    *(uint2*)(dst + 2 * stride) = ul;
}

// dummy kernel: shifts the launch index so ncu's capture (index 3) lands on
// gemm_hmma_kernel next round. ~2us cost.
__global__ void noop_kernel() {}

// tokens [8192,1024] fp32 -> g_As [8192, 3072] bf16 (hi|mid|lo thirds)
__global__ __launch_bounds__(256) void split_tokens_kernel(const float* __restrict__ x)
{
    size_t i = (size_t)blockIdx.x * 256 + threadIdx.x;     // float4 index
    float4 v = ((const float4*)x)[i];
    size_t row = i >> 8;
    int    c4  = (int)(i & 255) * 4;
    split_store4s(v, g_As + row * KSPLIT + c4, TE);
}

// Wq/Wk [1024,1024] fp32 -> g_Ws [2][1024, 3072] bf16
__global__ __launch_bounds__(256) void split_w_kernel(const float* __restrict__ Wq,
                                                      const float* __restrict__ Wk)
{
    const float* W = (blockIdx.z == 0) ? Wq : Wk;
    size_t i = (size_t)blockIdx.x * 256 + threadIdx.x;
    float4 v = ((const float4*)W)[i];
    size_t row = i >> 8;
    int    c4  = (int)(i & 255) * 4;
    split_store4s(v, g_Ws + (size_t)blockIdx.z * TE * KSPLIT + row * KSPLIT + c4, TE);
}

// g_Q/g_K fp32 [8192,1024] -> per-head split [bh][512][3*64] bf16
__global__ __launch_bounds__(256) void split_qk_kernel()
{
    const float*    src = blockIdx.z ? g_K : g_Q;
    __nv_bfloat16*  dst = blockIdx.z ? g_Ks2 : g_Qs2;
    size_t i = (size_t)blockIdx.x * 256 + threadIdx.x;     // float4 idx (2,097,152)
    float4 v = ((const float4*)src)[i];
    size_t r = i >> 8;
    int    c4 = (int)(i & 255) * 4;
    int h = c4 >> 6, d = c4 & 63;
    int b = (int)(r >> 9), s = (int)(r & 511);
    __nv_bfloat16* o = dst + (((size_t)(b * TH + h) * TS + s) * 192 + d);
    split_store4s(v, o, 64);
}

// ---------------------------------------------------------------------------
// HMMA GEMM (validated): 6-term bf16-split product
// ---------------------------------------------------------------------------
#define GEMM_STAGES 3
#define GEMM_STAGE_BYTES 32768
#define GEMM_SMEM (GEMM_STAGES * GEMM_STAGE_BYTES)
#define NCHUNK 96

__global__ __launch_bounds__(256) void gemm_hmma_kernel(const float* __restrict__ bq,
                                                        const float* __restrict__ bk)
{
    extern __shared__ char dsm[];
    const uint32_t smem_base = smem_u32(dsm);

    const int t    = threadIdx.x;
    const int lane = t & 31, wid = t >> 5;
    const int warp_m = wid & 3;
    const int warp_n = wid >> 2;
    const int sel = blockIdx.z;
    const int m0  = blockIdx.y * 128;
    const int n0  = blockIdx.x * 128;

    float*       C    = sel ? g_K : g_Q;
    const float* bias = sel ? bk : bq;

    const int row  = t >> 1;
    const int half = t & 1;
    const char* aG = (const char*)(g_As + (size_t)(m0 + row) * KSPLIT + half * 32);
    const char* bG = (const char*)(g_Ws + (size_t)sel * TE * KSPLIT
                                        + (size_t)(n0 + row) * KSPLIT + half * 32);
    uint32_t dOffA[4], dOffB[4];
#pragma unroll
    for (int i = 0; i < 4; i++) {
        uint32_t o = SW128((uint32_t)(row * 128 + half * 64 + i * 16));
        dOffA[i] = o;
        dOffB[i] = 16384u + o;
    }
    const uint32_t segA = 0x0010210u;   // [0,1,2,0,1,0]
    const uint32_t segB = 0x0211000u;   // [0,0,0,1,1,2]

#define ISSUE_STAGE(c_) do {                                                   \
    int _c = (c_);                                                             \
    int _seg = _c >> 4, _kc = _c & 15;                                         \
    int _pa = (segA >> (_seg * 4)) & 7, _pb = (segB >> (_seg * 4)) & 7;        \
    uint32_t _sb = smem_base + (_c % GEMM_STAGES) * GEMM_STAGE_BYTES;          \
    const char* _as = aG + (_pa * 1024 + _kc * 64) * 2;                        \
    const char* _bs = bG + (_pb * 1024 + _kc * 64) * 2;                        \
    _Pragma("unroll")                                                          \
    for (int _i = 0; _i < 4; _i++) {                                           \
        CP_ASYNC16(_sb + dOffA[_i], _as + _i * 16);                            \
        CP_ASYNC16(_sb + dOffB[_i], _bs + _i * 16);                            \
    }                                                                          \
    CP_COMMIT();                                                               \
} while (0)

    float acc[2][8][4];
#pragma unroll
    for (int i = 0; i < 2; i++)
#pragma unroll
        for (int j = 0; j < 8; j++)
#pragma unroll
            for (int k = 0; k < 4; k++) acc[i][j][k] = 0.f;

    const uint32_t lrow = lane & 15;
    const uint32_t lcol = (lane >> 4) * 16;

    ISSUE_STAGE(0);
    ISSUE_STAGE(1);

    for (int c = 0; c < NCHUNK; c++) {
        if (c < NCHUNK - 1) CP_WAIT1(); else CP_WAIT0();
        __syncthreads();
        if (c + 2 < NCHUNK) ISSUE_STAGE(c + 2);

        const uint32_t sb  = smem_base + (c % GEMM_STAGES) * GEMM_STAGE_BYTES;
        const uint32_t aRow = (uint32_t)(warp_m * 32) + lrow;
        const uint32_t bRow = (uint32_t)(warp_n * 64) + lrow;

#pragma unroll
        for (int kk = 0; kk < 4; kk++) {
            uint32_t a[2][4];
#pragma unroll
            for (int mt = 0; mt < 2; mt++) {
                uint32_t off = (aRow + mt * 16) * 128 + kk * 32 + lcol;
                LDSM_X4(a[mt][0], a[mt][1], a[mt][2], a[mt][3], sb + SW128(off));
            }
            uint32_t b[4][4];
#pragma unroll
            for (int nt2 = 0; nt2 < 4; nt2++) {
                uint32_t off = (bRow + nt2 * 16) * 128 + kk * 32 + lcol;
                LDSM_X4(b[nt2][0], b[nt2][1], b[nt2][2], b[nt2][3],
                        sb + 16384u + SW128(off));
            }
#pragma unroll
            for (int mt = 0; mt < 2; mt++)
#pragma unroll
                for (int nt2 = 0; nt2 < 4; nt2++) {
                    MMA_16816(acc[mt][nt2 * 2 + 0], a[mt], b[nt2][0], b[nt2][2]);
                    MMA_16816(acc[mt][nt2 * 2 + 1], a[mt], b[nt2][1], b[nt2][3]);
                }
        }
    }

    const int er = lane >> 2;
    const int ec = (lane & 3) * 2;
#pragma unroll
    for (int mt = 0; mt < 2; mt++) {
        const int r0 = m0 + warp_m * 32 + mt * 16 + er;
#pragma unroll
        for (int nt = 0; nt < 8; nt++) {
            const int col = n0 + warp_n * 64 + nt * 8 + ec;
            const float bx = bias[col], by = bias[col + 1];
            float* p = C + (size_t)r0 * TE + col;
            *(float2*)p            = make_float2(acc[mt][nt][0] + bx, acc[mt][nt][1] + by);
            *(float2*)(p + 8 * TE) = make_float2(acc[mt][nt][2] + bx, acc[mt][nt][3] + by);
        }
    }
#undef ISSUE_STAGE
}

// ---------------------------------------------------------------------------
// Attention-column kernel v5: HMMA scores + FMA-pipe exp (v4 was MUFU-bound:
// 67M expf @ 0.5 MUFU/cyc/SM ~= 515us chip floor; fast_expf removes it).
// ---------------------------------------------------------------------------
#define ES_STRIDE 514
#define OFF_QS  (64 * ES_STRIDE * 4)             // 131584
#define OFF_KS  (OFF_QS + 3 * 8192)              // +24576
#define OFF_COL (OFF_KS + 3 * 16384)             // +49152
#define OFF_DEN (OFF_COL + 512 * 8)
#define OFF_INV (OFF_DEN + 128 * 8)
#define ATTN_SMEM (OFF_INV + 64 * 8)

__global__ __launch_bounds__(256) void attn_col_kernel()
{
    extern __shared__ char sm[];
    const uint32_t sb = smem_u32(sm);
    float*  Es     = (float*)sm;
    double* colacc = (double*)(sm + OFF_COL);
    double* den2   = (double*)(sm + OFF_DEN);    // [64][2]
    double* invd   = (double*)(sm + OFF_INV);    // [64]

    const int t = threadIdx.x, lane = t & 31, wid = t >> 5;
    const int wm = wid & 3, wn = wid >> 2;
    const int bh = blockIdx.x;

    const __nv_bfloat16* Qg = g_Qs2 + (size_t)bh * TS * 192;
    const __nv_bfloat16* Kg = g_Ks2 + (size_t)bh * TS * 192;

    colacc[t] = 0.0;
    colacc[t + 256] = 0.0;

    const uint32_t lrow = lane & 15;
    const uint32_t lcol = (lane >> 4) * 16;
    const int fr = lane >> 2;
    const int fc = (lane & 3) * 2;
    const int segAa[6] = {0, 1, 2, 0, 1, 0};
    const int segBa[6] = {0, 0, 0, 1, 1, 2};

    for (int qt = 0; qt < 8; qt++) {
        __syncthreads();
        {
            int row = t >> 2, qq = t & 3;
            const char* src = (const char*)(Qg + (size_t)(qt * 64 + row) * 192) + qq * 96;
#pragma unroll
            for (int j = 0; j < 6; j++) {
                int i = qq * 6 + j;
                int seg = i >> 3, wi = (i & 7) * 16;
                CP_ASYNC16(sb + OFF_QS + seg * 8192 + SW128(row * 128 + wi), src + j * 16);
            }
        }
        CP_COMMIT();
        if (t < 128) den2[t] = 0.0;

        for (int kt = 0; kt < 4; kt++) {
            __syncthreads();
            {
                int row = t >> 1, hf = t & 1;
                const char* src = (const char*)(Kg + (size_t)(kt * 128 + row) * 192) + hf * 192;
#pragma unroll
                for (int j = 0; j < 12; j++) {
                    int i = hf * 12 + j;
                    int seg = i >> 3, wi = (i & 7) * 16;
                    CP_ASYNC16(sb + OFF_KS + seg * 16384 + SW128(row * 128 + wi), src + j * 16);
                }
            }
            CP_COMMIT();
            CP_WAIT0();
            __syncthreads();

            float acc[8][4];
#pragma unroll
            for (int i = 0; i < 8; i++)
#pragma unroll
                for (int k = 0; k < 4; k++) acc[i][k] = 0.f;

#pragma unroll
            for (int ch = 0; ch < 6; ch++) {
                const uint32_t abase = sb + OFF_QS + segAa[ch] * 8192;
                const uint32_t bbase = sb + OFF_KS + segBa[ch] * 16384;
#pragma unroll
                for (int kk = 0; kk < 4; kk++) {
                    uint32_t a[4];
                    LDSM_X4(a[0], a[1], a[2], a[3],
                            abase + SW128((wm * 16 + lrow) * 128 + kk * 32 + lcol));
                    uint32_t b[4][4];
#pragma unroll
                    for (int nt2 = 0; nt2 < 4; nt2++)
                        LDSM_X4(b[nt2][0], b[nt2][1], b[nt2][2], b[nt2][3],
                                bbase + SW128((wn * 64 + nt2 * 16 + lrow) * 128 + kk * 32 + lcol));
#pragma unroll
                    for (int nt2 = 0; nt2 < 4; nt2++) {
                        MMA_16816(acc[nt2 * 2 + 0], a, b[nt2][0], b[nt2][2]);
                        MMA_16816(acc[nt2 * 2 + 1], a, b[nt2][1], b[nt2][3]);
                    }
                }
            }

            // epilogue: FMA-pipe exp, Es stores, fp64 row sums
            const int r0 = wm * 16 + fr;
            double d0 = 0.0, d1 = 0.0;
#pragma unroll
            for (int nt = 0; nt < 8; nt++) {
                const int col = kt * 128 + wn * 64 + nt * 8 + fc;
                float e0 = fast_expf(fmaf(acc[nt][0], 0.125f, 1.0f));
                float e1 = fast_expf(fmaf(acc[nt][1], 0.125f, 1.0f));
                float e2 = fast_expf(fmaf(acc[nt][2], 0.125f, 1.0f));
                float e3 = fast_expf(fmaf(acc[nt][3], 0.125f, 1.0f));
                *(float2*)&Es[r0 * ES_STRIDE + col]       = make_float2(e0, e1);
                *(float2*)&Es[(r0 + 8) * ES_STRIDE + col] = make_float2(e2, e3);
                d0 += (double)e0 + (double)e1;
                d1 += (double)e2 + (double)e3;
            }
            d0 += __shfl_xor_sync(0xffffffffu, d0, 1);
            d0 += __shfl_xor_sync(0xffffffffu, d0, 2);
            d1 += __shfl_xor_sync(0xffffffffu, d1, 1);
            d1 += __shfl_xor_sync(0xffffffffu, d1, 2);
            if ((lane & 3) == 0) {
                den2[r0 * 2 + wn]       += d0;
                den2[(r0 + 8) * 2 + wn] += d1;
            }
        }

        __syncthreads();
        if (t < 64) invd[t] = 1.0 / (den2[t * 2] + den2[t * 2 + 1]);
        __syncthreads();

#pragma unroll
        for (int ss = 0; ss < 2; ss++) {
            int s = t + ss * 256;
            double a = colacc[s];
#pragma unroll 8
            for (int rr = 0; rr < 64; rr++)
                a = fma((double)Es[rr * ES_STRIDE + s], invd[rr], a);
            colacc[s] = a;
        }
    }

    g_colpart[(size_t)bh * TS + t]       = colacc[t];
    g_colpart[(size_t)bh * TS + t + 256] = colacc[t + 256];
}

// ---------------------------------------------------------------------------
// col -> log_softmax logits (fp64, deterministic tree reductions)
// ---------------------------------------------------------------------------
__global__ __launch_bounds__(512) void logits_kernel()
{
    __shared__ double red[512];
    const int b = blockIdx.x;
    const int s = threadIdx.x;

    double v = 0.0;
#pragma unroll
    for (int h = 0; h < TH; h++)
        v += g_colpart[((size_t)b * TH + h) * TS + s];

    red[s] = v;
    __syncthreads();
    for (int off = 256; off > 0; off >>= 1) {
        if (s < off) { double o = red[s + off]; if (o > red[s]) red[s] = o; }
        __syncthreads();
    }
    double m = red[0];
    __syncthreads();
    red[s] = exp(v - m);
    __syncthreads();
    for (int off = 256; off > 0; off >>= 1) {
        if (s < off) red[s] += red[s + off];
        __syncthreads();
    }
    double lse = m + log(red[0]);
    g_logits[(size_t)b * TS + s] = v - lse;
}

// ---------------------------------------------------------------------------
// Threefry-2x32 (JAX-exact, PARTITIONABLE): bits = o0 ^ o1, counter (0, i)
// ---------------------------------------------------------------------------
__device__ __forceinline__ void threefry2x32(
    unsigned k0, unsigned k1, unsigned x0, unsigned x1,
    unsigned& o0, unsigned& o1)
{
    const unsigned ks0 = k0, ks1 = k1, ks2 = k0 ^ k1 ^ 0x1BD11BDAu;
    x0 += ks0; x1 += ks1;
#define TF_RND(r) { x0 += x1; x1 = __funnelshift_l(x1, x1, r); x1 ^= x0; }
    TF_RND(13) TF_RND(15) TF_RND(26) TF_RND(6)   x0 += ks1; x1 += ks2 + 1u;
    TF_RND(17) TF_RND(29) TF_RND(16) TF_RND(24)  x0 += ks2; x1 += ks0 + 2u;
    TF_RND(13) TF_RND(15) TF_RND(26) TF_RND(6)   x0 += ks0; x1 += ks1 + 3u;
    TF_RND(17) TF_RND(29) TF_RND(16) TF_RND(24)  x0 += ks1; x1 += ks2 + 4u;
    TF_RND(13) TF_RND(15) TF_RND(26) TF_RND(6)   x0 += ks2; x1 += ks0 + 5u;
#undef TF_RND
    o0 = x0; o1 = x1;
}

// ---------------------------------------------------------------------------
// sample_kernel (validated R9): fp32 fast path + selective fp64 verification
// ---------------------------------------------------------------------------
__global__ __launch_bounds__(256) void sample_kernel(
    const float* __restrict__ tokens, float* __restrict__ out)
{
    const int warp = blockIdx.x * 8 + (threadIdx.x >> 5);   // 0..16383 = b*1024+j
    const int lane = threadIdx.x & 31;
    const int b = warp >> 10;
    const int j = warp & 1023;

    const double* lg = g_logits + (size_t)b * TS;

    float vreg[16];
    float best32 = -3.0e38f;
#pragma unroll
    for (int si = 0; si < 16; si++) {
        int s = lane + si * 32;
        unsigned i = (unsigned)warp * 512u + (unsigned)s;
        unsigned o0, o1;
        threefry2x32(0u, 42u, 0u, i, o0, o1);
        unsigned bits = o0 ^ o1;
        float f = __uint_as_float((bits >> 9) | 0x3f800000u) - 1.0f;
        float u = fmaxf(f, 1.17549435e-38f);
        float g32 = -logf(-logf(u));
        float v32 = g32 + (float)lg[s];
        vreg[si] = v32;
        best32 = fmaxf(best32, v32);
    }
#pragma unroll
    for (int off = 16; off > 0; off >>= 1)
        best32 = fmaxf(best32, __shfl_xor_sync(0xffffffffu, best32, off));

    const float thresh = best32 - 1.0e-4f;
    double best = -1.0e300;
    int    bi   = 0x7fffffff;
#pragma unroll
    for (int si = 0; si < 16; si++) {
        if (vreg[si] >= thresh) {
            int s = lane + si * 32;
            unsigned i = (unsigned)warp * 512u + (unsigned)s;
            unsigned o0, o1;
            threefry2x32(0u, 42u, 0u, i, o0, o1);
            unsigned bits = o0 ^ o1;
            float f = __uint_as_float((bits >> 9) | 0x3f800000u) - 1.0f;
            float u = fmaxf(f, 1.17549435e-38f);
            double g = -log(-log((double)u));        // EXACT round-3..11 formula
            double v = g + lg[s];
            if (v > best) { best = v; bi = s; }
        }
    }

#pragma unroll
    for (int off = 16; off > 0; off >>= 1) {
        double ov = __shfl_down_sync(0xffffffffu, best, off);
        int    oi = __shfl_down_sync(0xffffffffu, bi,   off);
        if (ov > best || (ov == best && oi < bi)) { best = ov; bi = oi; }
    }

    if (lane == 0)
        out[warp] = tokens[((size_t)b * TS + (size_t)bi) * TE + (size_t)j];
}

// ---------------------------------------------------------------------------
extern "C" void kernel_launch(void* const* d_in, const int* in_sizes, int n_in,
                              void* d_out, int out_size)
{
    (void)in_sizes; (void)n_in; (void)out_size;
    const float* tokens = (const float*)d_in[0];
    const float* Wq     = (const float*)d_in[1];
    const float* bq     = (const float*)d_in[2];
    const float* Wk     = (const float*)d_in[3];
    const float* bk     = (const float*)d_in[4];
    float* out = (float*)d_out;

    cudaFuncSetAttribute(gemm_hmma_kernel,
                         cudaFuncAttributeMaxDynamicSharedMemorySize, GEMM_SMEM);
    cudaFuncSetAttribute(attn_col_kernel,
                         cudaFuncAttributeMaxDynamicSharedMemorySize, ATTN_SMEM);

    noop_kernel<<<1, 32>>>();                              // launch 0 (profiler shim)
    split_tokens_kernel<<<8192, 256>>>(tokens);            // 1
    split_w_kernel<<<dim3(1024, 1, 2), 256>>>(Wq, Wk);     // 2
    gemm_hmma_kernel<<<dim3(8, 64, 2), 256, GEMM_SMEM>>>(bq, bk);   // 3 <- ncu capture
    split_qk_kernel<<<dim3(8192, 1, 2), 256>>>();          // 4
    attn_col_kernel<<<256, 256, ATTN_SMEM>>>();            // 5
    logits_kernel<<<16, 512>>>();                          // 6
    sample_kernel<<<2048, 256>>>(tokens, out);             // 7
}